// round 15
// baseline (speedup 1.0000x reference)
#include <cuda_runtime.h>
#include <math.h>

#define BB   64
#define HB   32                 // batches per pipeline half
#define SS   2048
#define DD   1024
#define HH   300
#define OO   2
#define SCH  16                 // s-chunks for the big reduction
#define SPC  (SS / SCH)         // 128 s per chunk
#define D4   (DD / 4)           // 256 float4 per row

// Scratch (allocation-free rule: __device__ globals)
__device__ int   g_end[BB];
__device__ float g_partial[BB][SCH][DD];
__device__ float g_euph[BB][DD];
__device__ float g_hidden[BB][HH];

// ---------------------------------------------------------------------------
// 1) end-index scan for ALL batches. end = first s with ids[b][s]==1,
//    fallback B (reference's except-path quirk).
// ---------------------------------------------------------------------------
__global__ __launch_bounds__(1024) void k_end(const int* __restrict__ ids) {
    cudaTriggerProgrammaticLaunchCompletion();
    int b = blockIdx.x;
    int t = threadIdx.x;
    __shared__ int m;
    if (t == 0) m = 0x7fffffff;
    __syncthreads();
    const int2* row = (const int2*)(ids + b * SS);
    int2 v = row[t];                       // 1024 threads * 2 ids = 2048
    if (v.x == 1) atomicMin(&m, 2 * t);
    if (v.y == 1) atomicMin(&m, 2 * t + 1);
    __syncthreads();
    if (t == 0) g_end[b] = (m == 0x7fffffff) ? BB : m;
}

// ---------------------------------------------------------------------------
// 2) masked segment-sum, s-chunk split, COMPACTED row list (~DRAM cap).
//    Handles HB batches starting at b0 (pipeline half).
// ---------------------------------------------------------------------------
__global__ __launch_bounds__(256) void k_reduce(const float* __restrict__ x,
                                                const float* __restrict__ mask,
                                                int b0) {
    cudaTriggerProgrammaticLaunchCompletion();
    int b = b0 + blockIdx.x;
    int c = blockIdx.y;
    int t = threadIdx.x;
    int s0 = c * SPC;

    // independent preamble: raw mask load (does not need g_end)
    float mraw = 0.0f;
    if (t < SPC) mraw = mask[b * SS + s0 + t];

    cudaGridDependencySynchronize();       // wait for upstream (k_end)
    int end = g_end[b];

    __shared__ float s_m[SPC];
    __shared__ int   s_idx[SPC];
    __shared__ int   s_cnt;
    if (t == 0) s_cnt = 0;
    __syncthreads();

    if (t < SPC && (s0 + t) < end && mraw != 0.0f) {
        int p = atomicAdd(&s_cnt, 1);
        s_idx[p] = t;
        s_m[p]   = mraw;
    }
    __syncthreads();
    int n = s_cnt;

    const float4* xp = (const float4*)(x + (long long)b * SS * DD)
                       + (long long)s0 * D4 + t;

    float4 acc = make_float4(0.f, 0.f, 0.f, 0.f);
    int i = 0;
    for (; i + 4 <= n; i += 4) {
        int   j0 = s_idx[i],     j1 = s_idx[i + 1];
        int   j2 = s_idx[i + 2], j3 = s_idx[i + 3];
        float m0 = s_m[i],       m1 = s_m[i + 1];
        float m2 = s_m[i + 2],   m3 = s_m[i + 3];
        float4 v0 = xp[j0 * D4];
        float4 v1 = xp[j1 * D4];
        float4 v2 = xp[j2 * D4];
        float4 v3 = xp[j3 * D4];
        acc.x += v0.x * m0; acc.y += v0.y * m0; acc.z += v0.z * m0; acc.w += v0.w * m0;
        acc.x += v1.x * m1; acc.y += v1.y * m1; acc.z += v1.z * m1; acc.w += v1.w * m1;
        acc.x += v2.x * m2; acc.y += v2.y * m2; acc.z += v2.z * m2; acc.w += v2.w * m2;
        acc.x += v3.x * m3; acc.y += v3.y * m3; acc.z += v3.z * m3; acc.w += v3.w * m3;
    }
    for (; i < n; i++) {
        int   j = s_idx[i];
        float m = s_m[i];
        float4 v = xp[j * D4];
        acc.x += v.x * m; acc.y += v.y * m; acc.z += v.z * m; acc.w += v.w * m;
    }
    ((float4*)g_partial[b][c])[t] = acc;
}

// ---------------------------------------------------------------------------
// 3) fold the SCH partials and divide by end. HB batches from b0.
// ---------------------------------------------------------------------------
__global__ __launch_bounds__(256) void k_combine(int b0) {
    cudaTriggerProgrammaticLaunchCompletion();
    int b = b0 + blockIdx.x;
    int d = blockIdx.y * 256 + threadIdx.x;
    cudaGridDependencySynchronize();
    float inv = 1.0f / (float)g_end[b];
    float acc = 0.f;
#pragma unroll
    for (int c = 0; c < SCH; c++)
        acc += g_partial[b][c][d];
    g_euph[b][d] = acc * inv;
}

// ---------------------------------------------------------------------------
// 4) hidden = tanh(euph @ W1^T + b1) for HB batches from b0.
//    Grid (16,75)=1200 blocks/half, warp-per-h, W1 row in regs, bTile 2.
// ---------------------------------------------------------------------------
__global__ __launch_bounds__(128) void k_hidden(const float* __restrict__ W1,
                                                const float* __restrict__ b1,
                                                int b0) {
    cudaTriggerProgrammaticLaunchCompletion();
    int warp = threadIdx.x >> 5;
    int lane = threadIdx.x & 31;
    int h    = blockIdx.y * 4 + warp;          // 75*4 = 300, always valid
    int bb   = b0 + blockIdx.x * 2;            // 16*2  = 32 per half

    const float4* w4p = (const float4*)(W1 + (long long)h * DD);
    float4 w[8];
#pragma unroll
    for (int i = 0; i < 8; i++) w[i] = w4p[lane + 32 * i];
    float bias = b1[h];

    cudaGridDependencySynchronize();           // wait for g_euph (this half)

#pragma unroll
    for (int bi = 0; bi < 2; bi++) {
        const float4* e4 = (const float4*)g_euph[bb + bi];
        float s = 0.f;
#pragma unroll
        for (int i = 0; i < 8; i++) {
            float4 e = e4[lane + 32 * i];
            s += e.x * w[i].x + e.y * w[i].y + e.z * w[i].z + e.w * w[i].w;
        }
#pragma unroll
        for (int off = 16; off > 0; off >>= 1)
            s += __shfl_xor_sync(0xffffffffu, s, off);
        if (lane == 0)
            g_hidden[bb + bi][h] = tanhf(s + bias);
    }
}

// ---------------------------------------------------------------------------
// 5) out = hidden @ W2^T + b2 for HB batches from b0. Warp per (b, o).
// ---------------------------------------------------------------------------
__global__ __launch_bounds__(512) void k_out(const float* __restrict__ W2,
                                             const float* __restrict__ b2,
                                             float* __restrict__ out,
                                             int b0) {
    int gw   = blockIdx.x * 16 + (threadIdx.x >> 5);   // 0..63 per half
    int lane = threadIdx.x & 31;
    int b    = b0 + (gw >> 1);
    int o    = gw & 1;

    const float* w = W2 + o * HH;
    float wr[10];                              // ceil(300/32)=10 per lane
#pragma unroll
    for (int i = 0; i < 10; i++) {
        int k = lane + 32 * i;
        wr[i] = (k < HH) ? w[k] : 0.0f;
    }
    float bias = b2[o];

    cudaGridDependencySynchronize();           // wait for g_hidden (this half)

    const float* hid = g_hidden[b];
    float s = 0.f;
#pragma unroll
    for (int i = 0; i < 10; i++) {
        int k = lane + 32 * i;
        if (k < HH) s += hid[k] * wr[i];
    }
#pragma unroll
    for (int off = 16; off > 0; off >>= 1)
        s += __shfl_xor_sync(0xffffffffu, s, off);
    if (lane == 0)
        out[b * OO + o] = s + bias;
}

// ---------------------------------------------------------------------------
template <typename... Args>
static inline void launch_pdl(cudaStream_t st, void (*kern)(Args...),
                              dim3 grid, dim3 block, Args... args) {
    cudaLaunchConfig_t cfg = {};
    cfg.gridDim  = grid;
    cfg.blockDim = block;
    cfg.stream   = st;
    cudaLaunchAttribute attr[1];
    attr[0].id = cudaLaunchAttributeProgrammaticStreamSerialization;
    attr[0].val.programmaticStreamSerializationAllowed = 1;
    cfg.attrs    = attr;
    cfg.numAttrs = 1;
    cudaLaunchKernelEx(&cfg, kern, args...);
}

extern "C" void kernel_launch(void* const* d_in, const int* in_sizes, int n_in,
                              void* d_out, int out_size) {
    const float* x    = (const float*)d_in[0];       // [B,S,D] f32
    const int*   ids  = (const int*)d_in[1];         // [B,S]   i32 (JAX x64 off)
    const float* mask = (const float*)d_in[2];       // [B,S,1] f32
    const float* W1   = (const float*)d_in[3];       // [H,D]
    const float* b1   = (const float*)d_in[4];       // [H]
    const float* W2   = (const float*)d_in[5];       // [OUT,H]
    const float* b2   = (const float*)d_in[6];       // [OUT]
    float*       out  = (float*)d_out;               // [B,OUT]

    // Lazily-created fork resources (first call = correctness run, outside
    // capture; subsequent captured calls reuse them -> identical graph).
    static cudaStream_t s1 = nullptr;
    static cudaEvent_t  e1 = nullptr, e2 = nullptr;
    if (s1 == nullptr) {
        cudaStreamCreateWithFlags(&s1, cudaStreamNonBlocking);
        cudaEventCreateWithFlags(&e1, cudaEventDisableTiming);
        cudaEventCreateWithFlags(&e2, cudaEventDisableTiming);
    }
    cudaStream_t s0 = 0;                   // captured stream

    // half 0 on s0
    k_end<<<BB, 1024>>>(ids);
    launch_pdl(s0, k_reduce, dim3(HB, SCH), dim3(256), x, mask, 0);
    cudaEventRecord(e1, s0);               // fork point: after red(0)

    launch_pdl(s0, k_combine, dim3(HB, 4), dim3(256), 0);
    launch_pdl(s0, k_hidden,  dim3(HB / 2, HH / 4), dim3(128), W1, b1, 0);
    launch_pdl(s0, k_out,     dim3(4), dim3(512), W2, b2, out, 0);

    // half 1 on s1: red(1) runs concurrently with tail(0)
    cudaStreamWaitEvent(s1, e1, 0);
    launch_pdl(s1, k_reduce, dim3(HB, SCH), dim3(256), x, mask, HB);
    launch_pdl(s1, k_combine, dim3(HB, 4), dim3(256), HB);
    launch_pdl(s1, k_hidden,  dim3(HB / 2, HH / 4), dim3(128), W1, b1, HB);
    launch_pdl(s1, k_out,     dim3(4), dim3(512), W2, b2, out, HB);
    cudaEventRecord(e2, s1);
    cudaStreamWaitEvent(s0, e2, 0);        // join back to captured stream
}

// round 17
// speedup vs baseline: 1.1646x; 1.1646x over previous
#include <cuda_runtime.h>
#include <math.h>

#define BB   64
#define SS   2048
#define DD   1024
#define HH   300
#define OO   2
#define SCH  16                 // s-chunks for the big reduction
#define SPC  (SS / SCH)         // 128 s per chunk
#define D4   (DD / 4)           // 256 float4 per row

// Scratch (allocation-free rule: __device__ globals)
__device__ int   g_end[BB];
__device__ int   g_done[BB];
__device__ float g_partial[BB][SCH][DD];
__device__ float g_euph[BB][DD];
__device__ float g_hidden[BB][HH];

// ---------------------------------------------------------------------------
// 1) end-index scan + reset g_done (graph replays reuse it). end = first s
//    with ids[b][s]==1, fallback B (reference's except-path quirk).
// ---------------------------------------------------------------------------
__global__ __launch_bounds__(1024) void k_end(const int* __restrict__ ids) {
    int b = blockIdx.x;
    int t = threadIdx.x;
    __shared__ int m;
    if (t == 0) { m = 0x7fffffff; g_done[b] = 0; }
    __syncthreads();
    const int2* row = (const int2*)(ids + b * SS);
    int2 v = row[t];                       // 1024 threads * 2 ids = 2048
    if (v.x == 1) atomicMin(&m, 2 * t);
    if (v.y == 1) atomicMin(&m, 2 * t + 1);
    __syncthreads();
    if (t == 0) g_end[b] = (m == 0x7fffffff) ? BB : m;
}

// ---------------------------------------------------------------------------
// 2) masked segment-sum, s-chunk split, COMPACTED row list (~DRAM cap), with
//    INLINE per-batch combine: the 16th-arriving block of batch b folds the
//    partials (L2-hot, overlapped with other blocks' streaming) and writes
//    g_euph directly. Handoff is the canonical threadFenceReduction pattern:
//    store -> fence (ALL threads) -> __syncthreads -> t0 release-atomic.
//    (R16 bug: the missing __syncthreads let t0's atomic race sibling warps'
//    stores.)
// ---------------------------------------------------------------------------
__global__ __launch_bounds__(256) void k_reduce(const float* __restrict__ x,
                                                const float* __restrict__ mask) {
    int b = blockIdx.x;
    int c = blockIdx.y;
    int t = threadIdx.x;
    int s0 = c * SPC;

    // independent preamble: raw mask load (does not need g_end)
    float mraw = 0.0f;
    if (t < SPC) mraw = mask[b * SS + s0 + t];

    cudaGridDependencySynchronize();       // wait for k_end
    int end = g_end[b];

    __shared__ float s_m[SPC];
    __shared__ int   s_idx[SPC];
    __shared__ int   s_cnt;
    __shared__ int   s_last;
    if (t == 0) s_cnt = 0;
    __syncthreads();

    if (t < SPC && (s0 + t) < end && mraw != 0.0f) {
        int p = atomicAdd(&s_cnt, 1);
        s_idx[p] = t;
        s_m[p]   = mraw;
    }
    __syncthreads();
    int n = s_cnt;

    const float4* xp = (const float4*)(x + (long long)b * SS * DD)
                       + (long long)s0 * D4 + t;

    float4 acc = make_float4(0.f, 0.f, 0.f, 0.f);
    int i = 0;
    for (; i + 4 <= n; i += 4) {
        int   j0 = s_idx[i],     j1 = s_idx[i + 1];
        int   j2 = s_idx[i + 2], j3 = s_idx[i + 3];
        float m0 = s_m[i],       m1 = s_m[i + 1];
        float m2 = s_m[i + 2],   m3 = s_m[i + 3];
        float4 v0 = xp[j0 * D4];
        float4 v1 = xp[j1 * D4];
        float4 v2 = xp[j2 * D4];
        float4 v3 = xp[j3 * D4];
        acc.x += v0.x * m0; acc.y += v0.y * m0; acc.z += v0.z * m0; acc.w += v0.w * m0;
        acc.x += v1.x * m1; acc.y += v1.y * m1; acc.z += v1.z * m1; acc.w += v1.w * m1;
        acc.x += v2.x * m2; acc.y += v2.y * m2; acc.z += v2.z * m2; acc.w += v2.w * m2;
        acc.x += v3.x * m3; acc.y += v3.y * m3; acc.z += v3.z * m3; acc.w += v3.w * m3;
    }
    for (; i < n; i++) {
        int   j = s_idx[i];
        float m = s_m[i];
        float4 v = xp[j * D4];
        acc.x += v.x * m; acc.y += v.y * m; acc.z += v.z * m; acc.w += v.w * m;
    }
    ((float4*)g_partial[b][c])[t] = acc;

    // --- release: every thread fences its store, then block syncs, then t0
    //     publishes via atomic ---
    __threadfence();
    __syncthreads();
    if (t == 0)
        s_last = (atomicAdd(&g_done[b], 1) == SCH - 1);
    __syncthreads();

    // --- last-arriver folds this batch's 16 partials into g_euph ---
    if (s_last) {
        __threadfence();                   // acquire side of the handoff
        float4 r = make_float4(0.f, 0.f, 0.f, 0.f);
#pragma unroll
        for (int k = 0; k < SCH; k++) {
            float4 v = ((const float4*)g_partial[b][k])[t];
            r.x += v.x; r.y += v.y; r.z += v.z; r.w += v.w;
        }
        float inv = 1.0f / (float)end;
        r.x *= inv; r.y *= inv; r.z *= inv; r.w *= inv;
        ((float4*)g_euph[b])[t] = r;
    }
}

// ---------------------------------------------------------------------------
// 3) hidden = tanh(euph @ W1^T + b1).  Grid (32,75)=2400 blocks (measured
//    optimum). W1 register prefetch pre-sync; syncs directly on k_reduce.
// ---------------------------------------------------------------------------
__global__ __launch_bounds__(128) void k_hidden(const float* __restrict__ W1,
                                                const float* __restrict__ b1) {
    int warp = threadIdx.x >> 5;
    int lane = threadIdx.x & 31;
    int h    = blockIdx.y * 4 + warp;          // 75*4 = 300, always valid
    int b0   = blockIdx.x * 2;                 // 32*2  = 64

    const float4* w4p = (const float4*)(W1 + (long long)h * DD);
    float4 w[8];
#pragma unroll
    for (int i = 0; i < 8; i++) w[i] = w4p[lane + 32 * i];
    float bias = b1[h];

    cudaGridDependencySynchronize();           // wait for g_euph (k_reduce)

#pragma unroll
    for (int bi = 0; bi < 2; bi++) {
        const float4* e4 = (const float4*)g_euph[b0 + bi];
        float s = 0.f;
#pragma unroll
        for (int i = 0; i < 8; i++) {
            float4 e = e4[lane + 32 * i];
            s += e.x * w[i].x + e.y * w[i].y + e.z * w[i].z + e.w * w[i].w;
        }
#pragma unroll
        for (int off = 16; off > 0; off >>= 1)
            s += __shfl_xor_sync(0xffffffffu, s, off);
        if (lane == 0)
            g_hidden[b0 + bi][h] = tanhf(s + bias);
    }
}

// ---------------------------------------------------------------------------
// 4) out = hidden @ W2^T + b2.  Warp per (b, o): 128 warps over 8 blocks.
//    W2 slice prefetched pre-sync.
// ---------------------------------------------------------------------------
__global__ __launch_bounds__(512) void k_out(const float* __restrict__ W2,
                                             const float* __restrict__ b2,
                                             float* __restrict__ out) {
    int gw   = blockIdx.x * 16 + (threadIdx.x >> 5);   // 0..127
    int lane = threadIdx.x & 31;
    int b    = gw >> 1;
    int o    = gw & 1;

    const float* w = W2 + o * HH;
    float wr[10];                              // ceil(300/32)=10 per lane
#pragma unroll
    for (int i = 0; i < 10; i++) {
        int k = lane + 32 * i;
        wr[i] = (k < HH) ? w[k] : 0.0f;
    }
    float bias = b2[o];

    cudaGridDependencySynchronize();           // wait for g_hidden

    const float* hid = g_hidden[b];
    float s = 0.f;
#pragma unroll
    for (int i = 0; i < 10; i++) {
        int k = lane + 32 * i;
        if (k < HH) s += hid[k] * wr[i];
    }
#pragma unroll
    for (int off = 16; off > 0; off >>= 1)
        s += __shfl_xor_sync(0xffffffffu, s, off);
    if (lane == 0)
        out[b * OO + o] = s + bias;
}

// ---------------------------------------------------------------------------
template <typename... Args>
static inline void launch_pdl(void (*kern)(Args...), dim3 grid, dim3 block,
                              Args... args) {
    cudaLaunchConfig_t cfg = {};
    cfg.gridDim  = grid;
    cfg.blockDim = block;
    cudaLaunchAttribute attr[1];
    attr[0].id = cudaLaunchAttributeProgrammaticStreamSerialization;
    attr[0].val.programmaticStreamSerializationAllowed = 1;
    cfg.attrs    = attr;
    cfg.numAttrs = 1;
    cudaLaunchKernelEx(&cfg, kern, args...);
}

extern "C" void kernel_launch(void* const* d_in, const int* in_sizes, int n_in,
                              void* d_out, int out_size) {
    const float* x    = (const float*)d_in[0];       // [B,S,D] f32
    const int*   ids  = (const int*)d_in[1];         // [B,S]   i32 (JAX x64 off)
    const float* mask = (const float*)d_in[2];       // [B,S,1] f32
    const float* W1   = (const float*)d_in[3];       // [H,D]
    const float* b1   = (const float*)d_in[4];       // [H]
    const float* W2   = (const float*)d_in[5];       // [OUT,H]
    const float* b2   = (const float*)d_in[6];       // [OUT]
    float*       out  = (float*)d_out;               // [B,OUT]

    k_end<<<BB, 1024>>>(ids);
    launch_pdl(k_reduce, dim3(BB, SCH), dim3(256), x, mask);
    launch_pdl(k_hidden, dim3(32, HH / 4), dim3(128), W1, b1);
    launch_pdl(k_out,    dim3(8), dim3(512), W2, b2, out);
}